// round 1
// baseline (speedup 1.0000x reference)
#include <cuda_runtime.h>

#define N_NODES 100000
#define C 256
#define EPS 1e-5f

// Scratch (device globals — no runtime allocation allowed)
__device__ float g_xw[(size_t)N_NODES * C];
__device__ float g_agg[(size_t)N_NODES * C];
__device__ float g_deg[N_NODES];
__device__ float g_inv[N_NODES];

static inline int cdiv(int a, int b) { return (a + b - 1) / b; }

__device__ __forceinline__ void red_add_v4(float* addr, float4 v) {
    asm volatile("red.global.add.v4.f32 [%0], {%1, %2, %3, %4};"
                 :: "l"(addr), "f"(v.x), "f"(v.y), "f"(v.z), "f"(v.w)
                 : "memory");
}

// ---------------------------------------------------------------------------
// Degree / normalization
// ---------------------------------------------------------------------------
__global__ void k_deg_init(float* deg, int n) {
    int i = blockIdx.x * blockDim.x + threadIdx.x;
    if (i < n) deg[i] = 1.0f;   // self-loop contributes 1
}

__global__ void k_deg_count(const int* __restrict__ col, float* deg, int E) {
    int i = blockIdx.x * blockDim.x + threadIdx.x;
    if (i < E) atomicAdd(&deg[col[i]], 1.0f);
}

__global__ void k_inv(const float* __restrict__ deg, float* __restrict__ inv, int n) {
    int i = blockIdx.x * blockDim.x + threadIdx.x;
    if (i < n) inv[i] = rsqrtf(deg[i]);
}

// ---------------------------------------------------------------------------
// fp32 GEMM: C[M,256] = A[M,256] @ B[256,256]   (row-major)
// 128x128 block tile, BK=8, 256 threads, 8x8 per-thread micro-tile.
// ---------------------------------------------------------------------------
__global__ __launch_bounds__(256) void k_gemm(const float* __restrict__ A,
                                              const float* __restrict__ B,
                                              float* __restrict__ Cmat, int M) {
    __shared__ float As[8][132];   // [k][m], padded row stride (528B, 16B-aligned)
    __shared__ float Bs[8][128];   // [k][n]

    const int tid = threadIdx.x;
    const int bm = blockIdx.y * 128;
    const int bn = blockIdx.x * 128;

    const int tr = (tid >> 4) * 8;     // row offset in tile (0..120)
    const int tc = (tid & 15) * 8;     // col offset in tile (0..120)

    const int a_r = tid >> 1;          // 0..127
    const int a_c = (tid & 1) * 4;     // 0 or 4
    const int b_r = tid >> 5;          // 0..7
    const int b_c = (tid & 31) * 4;    // 0..124

    const int arow = bm + a_r;
    const bool avalid = arow < M;

    float acc[8][8];
#pragma unroll
    for (int i = 0; i < 8; i++)
#pragma unroll
        for (int j = 0; j < 8; j++) acc[i][j] = 0.f;

    for (int k0 = 0; k0 < C; k0 += 8) {
        float4 a = make_float4(0.f, 0.f, 0.f, 0.f);
        if (avalid) a = *(const float4*)(A + (size_t)arow * C + k0 + a_c);
        As[a_c + 0][a_r] = a.x;
        As[a_c + 1][a_r] = a.y;
        As[a_c + 2][a_r] = a.z;
        As[a_c + 3][a_r] = a.w;
        *(float4*)&Bs[b_r][b_c] = *(const float4*)(B + (size_t)(k0 + b_r) * C + bn + b_c);
        __syncthreads();

#pragma unroll
        for (int k = 0; k < 8; k++) {
            float ar[8], br[8];
#pragma unroll
            for (int i = 0; i < 8; i++) ar[i] = As[k][tr + i];
#pragma unroll
            for (int j = 0; j < 8; j++) br[j] = Bs[k][tc + j];
#pragma unroll
            for (int i = 0; i < 8; i++)
#pragma unroll
                for (int j = 0; j < 8; j++) acc[i][j] += ar[i] * br[j];
        }
        __syncthreads();
    }

#pragma unroll
    for (int i = 0; i < 8; i++) {
        int r = bm + tr + i;
        if (r < M) {
            *(float4*)(Cmat + (size_t)r * C + bn + tc) =
                make_float4(acc[i][0], acc[i][1], acc[i][2], acc[i][3]);
            *(float4*)(Cmat + (size_t)r * C + bn + tc + 4) =
                make_float4(acc[i][4], acc[i][5], acc[i][6], acc[i][7]);
        }
    }
}

// ---------------------------------------------------------------------------
// agg[i,:] = bias + xw[i,:] * inv[i]^2   (self-loop term + bias, no atomics)
// one thread per float4
// ---------------------------------------------------------------------------
__global__ void k_agg_init(const float* __restrict__ xw, const float* __restrict__ inv,
                           const float* __restrict__ bias, float* __restrict__ agg) {
    int idx = blockIdx.x * blockDim.x + threadIdx.x;   // N*C/4 total
    int node = idx >> 6;           // 64 float4 per row
    int c4 = idx & 63;
    if (node >= N_NODES) return;
    float s = inv[node];
    s = s * s;
    float4 v = *(const float4*)(xw + (size_t)node * C + c4 * 4);
    float4 b = *(const float4*)(bias + c4 * 4);
    float4 o = make_float4(fmaf(v.x, s, b.x), fmaf(v.y, s, b.y),
                           fmaf(v.z, s, b.z), fmaf(v.w, s, b.w));
    *(float4*)(agg + (size_t)node * C + c4 * 4) = o;
}

// ---------------------------------------------------------------------------
// Edge scatter: one warp per edge, 8 floats per lane (2 float4).
// agg[col,:] += xw[row,:] * inv[row]*inv[col]
// ---------------------------------------------------------------------------
__global__ __launch_bounds__(256) void k_edge_scatter(const float* __restrict__ xw,
                                                      const int* __restrict__ row,
                                                      const int* __restrict__ col,
                                                      const float* __restrict__ inv,
                                                      float* __restrict__ agg, int E) {
    int e = (blockIdx.x * blockDim.x + threadIdx.x) >> 5;
    int lane = threadIdx.x & 31;
    if (e >= E) return;
    int r = __ldg(row + e);
    int c = __ldg(col + e);
    float norm = __ldg(inv + r) * __ldg(inv + c);

    const float4* src = (const float4*)(xw + (size_t)r * C);
    float* dst = agg + (size_t)c * C;

    float4 a = __ldg(src + lane);
    float4 b = __ldg(src + lane + 32);
    a.x *= norm; a.y *= norm; a.z *= norm; a.w *= norm;
    b.x *= norm; b.y *= norm; b.z *= norm; b.w *= norm;
    red_add_v4(dst + lane * 4, a);
    red_add_v4(dst + 128 + lane * 4, b);
}

// ---------------------------------------------------------------------------
// LayerNorm + ReLU, one warp per row (256 elems, 8 per lane)
// ---------------------------------------------------------------------------
__global__ __launch_bounds__(256) void k_ln_relu(const float* __restrict__ in,
                                                 const float* __restrict__ gamma,
                                                 const float* __restrict__ beta,
                                                 float* __restrict__ out) {
    int w = (blockIdx.x * blockDim.x + threadIdx.x) >> 5;
    int lane = threadIdx.x & 31;
    if (w >= N_NODES) return;

    const float4* r = (const float4*)(in + (size_t)w * C);
    float4 v0 = r[lane];
    float4 v1 = r[lane + 32];

    float s = v0.x + v0.y + v0.z + v0.w + v1.x + v1.y + v1.z + v1.w;
#pragma unroll
    for (int o = 16; o > 0; o >>= 1) s += __shfl_xor_sync(0xFFFFFFFFu, s, o);
    float mu = s * (1.0f / 256.0f);

    float d, ss = 0.f;
    d = v0.x - mu; ss += d * d;
    d = v0.y - mu; ss += d * d;
    d = v0.z - mu; ss += d * d;
    d = v0.w - mu; ss += d * d;
    d = v1.x - mu; ss += d * d;
    d = v1.y - mu; ss += d * d;
    d = v1.z - mu; ss += d * d;
    d = v1.w - mu; ss += d * d;
#pragma unroll
    for (int o = 16; o > 0; o >>= 1) ss += __shfl_xor_sync(0xFFFFFFFFu, ss, o);
    float rstd = rsqrtf(ss * (1.0f / 256.0f) + EPS);

    float4 g0 = ((const float4*)gamma)[lane];
    float4 g1 = ((const float4*)gamma)[lane + 32];
    float4 e0 = ((const float4*)beta)[lane];
    float4 e1 = ((const float4*)beta)[lane + 32];

    float4 o0, o1;
    o0.x = fmaxf(0.f, (v0.x - mu) * rstd * g0.x + e0.x);
    o0.y = fmaxf(0.f, (v0.y - mu) * rstd * g0.y + e0.y);
    o0.z = fmaxf(0.f, (v0.z - mu) * rstd * g0.z + e0.z);
    o0.w = fmaxf(0.f, (v0.w - mu) * rstd * g0.w + e0.w);
    o1.x = fmaxf(0.f, (v1.x - mu) * rstd * g1.x + e1.x);
    o1.y = fmaxf(0.f, (v1.y - mu) * rstd * g1.y + e1.y);
    o1.z = fmaxf(0.f, (v1.z - mu) * rstd * g1.z + e1.z);
    o1.w = fmaxf(0.f, (v1.w - mu) * rstd * g1.w + e1.w);

    float4* po = (float4*)(out + (size_t)w * C);
    po[lane] = o0;
    po[lane + 32] = o1;
}

// ---------------------------------------------------------------------------
// Launch
// ---------------------------------------------------------------------------
static void run_layer(const float* xin, const float* W, const float* bias,
                      const int* edges, int E,
                      float* xw, float* agg, const float* inv,
                      const float* gamma, const float* beta, float* zout) {
    dim3 ggrid(2, cdiv(N_NODES, 128));
    k_gemm<<<ggrid, 256>>>(xin, W, xw, N_NODES);

    int n4 = N_NODES * (C / 4);
    k_agg_init<<<cdiv(n4, 256), 256>>>(xw, inv, bias, agg);

    long long lanes = (long long)E * 32;
    k_edge_scatter<<<(int)((lanes + 255) / 256), 256>>>(xw, edges, edges + E, inv, agg, E);

    k_ln_relu<<<cdiv(N_NODES * 32, 256), 256>>>(agg, gamma, beta, zout);
}

extern "C" void kernel_launch(void* const* d_in, const int* in_sizes, int n_in,
                              void* d_out, int out_size) {
    const float* x     = (const float*)d_in[0];
    const int*   edges = (const int*)d_in[1];
    const float* W1    = (const float*)d_in[2];
    const float* b1    = (const float*)d_in[3];
    const float* W2    = (const float*)d_in[4];
    const float* b2    = (const float*)d_in[5];
    const float* gamma = (const float*)d_in[6];
    const float* beta  = (const float*)d_in[7];
    const int E = in_sizes[1] / 2;

    float *xw, *agg, *deg, *inv;
    cudaGetSymbolAddress((void**)&xw,  g_xw);
    cudaGetSymbolAddress((void**)&agg, g_agg);
    cudaGetSymbolAddress((void**)&deg, g_deg);
    cudaGetSymbolAddress((void**)&inv, g_inv);

    float* z1 = (float*)d_out;
    float* z2 = (float*)d_out + (size_t)N_NODES * C;

    k_deg_init<<<cdiv(N_NODES, 256), 256>>>(deg, N_NODES);
    k_deg_count<<<cdiv(E, 256), 256>>>(edges + E, deg, E);
    k_inv<<<cdiv(N_NODES, 256), 256>>>(deg, inv, N_NODES);

    run_layer(x,  W1, b1, edges, E, xw, agg, inv, gamma, beta, z1);
    run_layer(z1, W2, b2, edges, E, xw, agg, inv, gamma, beta, z2);
}

// round 2
// speedup vs baseline: 1.5132x; 1.5132x over previous
#include <cuda_runtime.h>

#define N_NODES 100000
#define C 256
#define EPS 1e-5f
#define E_MAX 1700000

// Scratch (device globals — no runtime allocation allowed)
__device__ float g_xw[(size_t)N_NODES * C];
__device__ float g_inv[N_NODES];
__device__ int   g_cnt[N_NODES];
__device__ int   g_cursor[N_NODES];
__device__ int   g_start[N_NODES + 1];
__device__ int   g_ebuf[E_MAX];

static inline int cdiv(int a, int b) { return (a + b - 1) / b; }

// ---------------------------------------------------------------------------
// CSR build: histogram, inv-sqrt-degree, scan, bucket
// ---------------------------------------------------------------------------
__global__ void k_zero(int* cnt, int* cursor, int n) {
    int i = blockIdx.x * blockDim.x + threadIdx.x;
    if (i < n) { cnt[i] = 0; cursor[i] = 0; }
}

__global__ void k_hist(const int* __restrict__ col, int* cnt, int E) {
    int i = blockIdx.x * blockDim.x + threadIdx.x;
    if (i < E) atomicAdd(&cnt[col[i]], 1);
}

__global__ void k_inv(const int* __restrict__ cnt, float* __restrict__ inv, int n) {
    int i = blockIdx.x * blockDim.x + threadIdx.x;
    if (i < n) inv[i] = rsqrtf((float)cnt[i] + 1.0f);   // +1 self loop
}

// Single-block exclusive scan of cnt[0..n-1] -> start[0..n]
__global__ __launch_bounds__(1024) void k_scan(const int* __restrict__ cnt,
                                               int* __restrict__ start, int n) {
    __shared__ int sums[1024];
    const int t = threadIdx.x;
    const int chunk = (n + 1023) / 1024;
    const int lo = t * chunk;
    const int hi = min(lo + chunk, n);

    int s = 0;
    for (int i = lo; i < hi; i++) s += cnt[i];
    sums[t] = s;
    __syncthreads();

    // Hillis-Steele inclusive scan
    for (int off = 1; off < 1024; off <<= 1) {
        int v = (t >= off) ? sums[t - off] : 0;
        __syncthreads();
        sums[t] += v;
        __syncthreads();
    }

    int run = (t == 0) ? 0 : sums[t - 1];
    for (int i = lo; i < hi; i++) { start[i] = run; run += cnt[i]; }
    if (t == 1023) start[n] = sums[1023];
}

__global__ void k_bucket(const int* __restrict__ row, const int* __restrict__ col,
                         const int* __restrict__ start, int* cursor,
                         int* __restrict__ ebuf, int E) {
    int i = blockIdx.x * blockDim.x + threadIdx.x;
    if (i < E) {
        int c = col[i];
        int p = atomicAdd(&cursor[c], 1);
        ebuf[start[c] + p] = row[i];
    }
}

// ---------------------------------------------------------------------------
// fp32 GEMM: C[M,256] = A[M,256] @ B[256,256]   (row-major)
// 128x128 block tile, BK=8, 256 threads, 8x8 micro-tile, LDS.128 shared reads.
// ---------------------------------------------------------------------------
__global__ __launch_bounds__(256) void k_gemm(const float* __restrict__ A,
                                              const float* __restrict__ B,
                                              float* __restrict__ Cmat, int M) {
    __shared__ float As[8][132];   // [k][m], padded row stride (528B, 16B-aligned)
    __shared__ float Bs[8][128];   // [k][n]

    const int tid = threadIdx.x;
    const int bm = blockIdx.y * 128;
    const int bn = blockIdx.x * 128;

    const int tr = (tid >> 4) * 8;
    const int tc = (tid & 15) * 8;

    const int a_r = tid >> 1;
    const int a_c = (tid & 1) * 4;
    const int b_r = tid >> 5;
    const int b_c = (tid & 31) * 4;

    const int arow = bm + a_r;
    const bool avalid = arow < M;

    float acc[8][8];
#pragma unroll
    for (int i = 0; i < 8; i++)
#pragma unroll
        for (int j = 0; j < 8; j++) acc[i][j] = 0.f;

    for (int k0 = 0; k0 < C; k0 += 8) {
        float4 a = make_float4(0.f, 0.f, 0.f, 0.f);
        if (avalid) a = *(const float4*)(A + (size_t)arow * C + k0 + a_c);
        As[a_c + 0][a_r] = a.x;
        As[a_c + 1][a_r] = a.y;
        As[a_c + 2][a_r] = a.z;
        As[a_c + 3][a_r] = a.w;
        *(float4*)&Bs[b_r][b_c] = *(const float4*)(B + (size_t)(k0 + b_r) * C + bn + b_c);
        __syncthreads();

#pragma unroll
        for (int k = 0; k < 8; k++) {
            float4 a0 = *(const float4*)&As[k][tr];
            float4 a1 = *(const float4*)&As[k][tr + 4];
            float4 b0 = *(const float4*)&Bs[k][tc];
            float4 b1 = *(const float4*)&Bs[k][tc + 4];
            float ar[8] = {a0.x, a0.y, a0.z, a0.w, a1.x, a1.y, a1.z, a1.w};
            float br[8] = {b0.x, b0.y, b0.z, b0.w, b1.x, b1.y, b1.z, b1.w};
#pragma unroll
            for (int i = 0; i < 8; i++)
#pragma unroll
                for (int j = 0; j < 8; j++) acc[i][j] = fmaf(ar[i], br[j], acc[i][j]);
        }
        __syncthreads();
    }

#pragma unroll
    for (int i = 0; i < 8; i++) {
        int r = bm + tr + i;
        if (r < M) {
            *(float4*)(Cmat + (size_t)r * C + bn + tc) =
                make_float4(acc[i][0], acc[i][1], acc[i][2], acc[i][3]);
            *(float4*)(Cmat + (size_t)r * C + bn + tc + 4) =
                make_float4(acc[i][4], acc[i][5], acc[i][6], acc[i][7]);
        }
    }
}

// ---------------------------------------------------------------------------
// Fused aggregation + LayerNorm + ReLU.
// One warp per node: acc = bias + xw[n]*inv[n]^2 + sum_{r in N(n)} xw[r]*inv[r]*inv[n]
// then LN+ReLU, single write of z.
// ---------------------------------------------------------------------------
__global__ __launch_bounds__(256) void k_agg_ln(const float* __restrict__ xw,
                                                const int* __restrict__ ebuf,
                                                const int* __restrict__ start,
                                                const float* __restrict__ inv,
                                                const float* __restrict__ bias,
                                                const float* __restrict__ gamma,
                                                const float* __restrict__ beta,
                                                float* __restrict__ out) {
    int w = (blockIdx.x * blockDim.x + threadIdx.x) >> 5;
    int lane = threadIdx.x & 31;
    if (w >= N_NODES) return;

    const float invn = __ldg(inv + w);

    // self-loop + bias
    const float4* self = (const float4*)(xw + (size_t)w * C);
    float4 a0 = __ldg(self + lane);
    float4 a1 = __ldg(self + lane + 32);
    float4 b0 = ((const float4*)bias)[lane];
    float4 b1 = ((const float4*)bias)[lane + 32];
    float sn = invn * invn;
    a0.x = fmaf(a0.x, sn, b0.x); a0.y = fmaf(a0.y, sn, b0.y);
    a0.z = fmaf(a0.z, sn, b0.z); a0.w = fmaf(a0.w, sn, b0.w);
    a1.x = fmaf(a1.x, sn, b1.x); a1.y = fmaf(a1.y, sn, b1.y);
    a1.z = fmaf(a1.z, sn, b1.z); a1.w = fmaf(a1.w, sn, b1.w);

    const int s = __ldg(start + w);
    const int e = __ldg(start + w + 1);

    for (int base = s; base < e; base += 32) {
        int rem = e - base;
        int r = 0; float nv = 0.f;
        if (lane < rem) {
            r = __ldg(ebuf + base + lane);
            nv = __ldg(inv + r) * invn;
        }
        int cnt = min(rem, 32);
#pragma unroll 2
        for (int j = 0; j < cnt; j++) {
            int rj = __shfl_sync(0xFFFFFFFFu, r, j);
            float nj = __shfl_sync(0xFFFFFFFFu, nv, j);
            const float4* src = (const float4*)(xw + (size_t)rj * C);
            float4 f0 = __ldg(src + lane);
            float4 f1 = __ldg(src + lane + 32);
            a0.x = fmaf(f0.x, nj, a0.x); a0.y = fmaf(f0.y, nj, a0.y);
            a0.z = fmaf(f0.z, nj, a0.z); a0.w = fmaf(f0.w, nj, a0.w);
            a1.x = fmaf(f1.x, nj, a1.x); a1.y = fmaf(f1.y, nj, a1.y);
            a1.z = fmaf(f1.z, nj, a1.z); a1.w = fmaf(f1.w, nj, a1.w);
        }
    }

    // LayerNorm + ReLU
    float su = a0.x + a0.y + a0.z + a0.w + a1.x + a1.y + a1.z + a1.w;
#pragma unroll
    for (int o = 16; o > 0; o >>= 1) su += __shfl_xor_sync(0xFFFFFFFFu, su, o);
    float mu = su * (1.0f / 256.0f);

    float d, ss = 0.f;
    d = a0.x - mu; ss += d * d;
    d = a0.y - mu; ss += d * d;
    d = a0.z - mu; ss += d * d;
    d = a0.w - mu; ss += d * d;
    d = a1.x - mu; ss += d * d;
    d = a1.y - mu; ss += d * d;
    d = a1.z - mu; ss += d * d;
    d = a1.w - mu; ss += d * d;
#pragma unroll
    for (int o = 16; o > 0; o >>= 1) ss += __shfl_xor_sync(0xFFFFFFFFu, ss, o);
    float rstd = rsqrtf(ss * (1.0f / 256.0f) + EPS);

    float4 g0 = ((const float4*)gamma)[lane];
    float4 g1 = ((const float4*)gamma)[lane + 32];
    float4 e0 = ((const float4*)beta)[lane];
    float4 e1 = ((const float4*)beta)[lane + 32];

    float4 o0, o1;
    o0.x = fmaxf(0.f, (a0.x - mu) * rstd * g0.x + e0.x);
    o0.y = fmaxf(0.f, (a0.y - mu) * rstd * g0.y + e0.y);
    o0.z = fmaxf(0.f, (a0.z - mu) * rstd * g0.z + e0.z);
    o0.w = fmaxf(0.f, (a0.w - mu) * rstd * g0.w + e0.w);
    o1.x = fmaxf(0.f, (a1.x - mu) * rstd * g1.x + e1.x);
    o1.y = fmaxf(0.f, (a1.y - mu) * rstd * g1.y + e1.y);
    o1.z = fmaxf(0.f, (a1.z - mu) * rstd * g1.z + e1.z);
    o1.w = fmaxf(0.f, (a1.w - mu) * rstd * g1.w + e1.w);

    float4* po = (float4*)(out + (size_t)w * C);
    po[lane] = o0;
    po[lane + 32] = o1;
}

// ---------------------------------------------------------------------------
// Launch
// ---------------------------------------------------------------------------
static void run_layer(const float* xin, const float* W, const float* bias,
                      float* xw, const int* ebuf, const int* start,
                      const float* inv, const float* gamma, const float* beta,
                      float* zout) {
    dim3 ggrid(2, cdiv(N_NODES, 128));
    k_gemm<<<ggrid, 256>>>(xin, W, xw, N_NODES);
    k_agg_ln<<<cdiv(N_NODES * 32, 256), 256>>>(xw, ebuf, start, inv, bias,
                                               gamma, beta, zout);
}

extern "C" void kernel_launch(void* const* d_in, const int* in_sizes, int n_in,
                              void* d_out, int out_size) {
    const float* x     = (const float*)d_in[0];
    const int*   edges = (const int*)d_in[1];
    const float* W1    = (const float*)d_in[2];
    const float* b1    = (const float*)d_in[3];
    const float* W2    = (const float*)d_in[4];
    const float* b2    = (const float*)d_in[5];
    const float* gamma = (const float*)d_in[6];
    const float* beta  = (const float*)d_in[7];
    const int E = in_sizes[1] / 2;
    const int* row = edges;
    const int* col = edges + E;

    float *xw, *inv;
    int *cnt, *cursor, *start, *ebuf;
    cudaGetSymbolAddress((void**)&xw,     g_xw);
    cudaGetSymbolAddress((void**)&inv,    g_inv);
    cudaGetSymbolAddress((void**)&cnt,    g_cnt);
    cudaGetSymbolAddress((void**)&cursor, g_cursor);
    cudaGetSymbolAddress((void**)&start,  g_start);
    cudaGetSymbolAddress((void**)&ebuf,   g_ebuf);

    float* z1 = (float*)d_out;
    float* z2 = (float*)d_out + (size_t)N_NODES * C;

    // CSR build
    k_zero<<<cdiv(N_NODES, 256), 256>>>(cnt, cursor, N_NODES);
    k_hist<<<cdiv(E, 256), 256>>>(col, cnt, E);
    k_inv<<<cdiv(N_NODES, 256), 256>>>(cnt, inv, N_NODES);
    k_scan<<<1, 1024>>>(cnt, start, N_NODES);
    k_bucket<<<cdiv(E, 256), 256>>>(row, col, start, cursor, ebuf, E);

    run_layer(x,  W1, b1, xw, ebuf, start, inv, gamma, beta, z1);
    run_layer(z1, W2, b2, xw, ebuf, start, inv, gamma, beta, z2);
}

// round 5
// speedup vs baseline: 2.4989x; 1.6514x over previous
#include <cuda_runtime.h>
#include <cuda_bf16.h>
#include <cstdint>

#define N_NODES 100000
#define C 256
#define EPS 1e-5f
#define E_MAX 1700000

// Scratch (device globals — no runtime allocation allowed)
__device__ float g_xw[(size_t)N_NODES * C];
__device__ float g_inv[N_NODES];
__device__ int   g_cnt[N_NODES];
__device__ int   g_cursor[N_NODES];
__device__ int   g_start[N_NODES + 1];
__device__ int   g_ebuf[E_MAX];
__device__ int   g_bsum[128];
__device__ __nv_bfloat16 g_bh[C * C];   // W^T hi, [n][k]
__device__ __nv_bfloat16 g_bl[C * C];   // W^T lo, [n][k]

static inline int cdiv(int a, int b) { return (a + b - 1) / b; }

__device__ __forceinline__ uint32_t pk(__nv_bfloat16 a, __nv_bfloat16 b) {
    __nv_bfloat162 t(a, b);
    return *(uint32_t*)&t;
}

#define MMA_BF16(c, a, b0, b1)                                                  \
    asm volatile("mma.sync.aligned.m16n8k16.row.col.f32.bf16.bf16.f32 "        \
                 "{%0,%1,%2,%3},{%4,%5,%6,%7},{%8,%9},{%0,%1,%2,%3};"          \
                 : "+f"((c)[0]), "+f"((c)[1]), "+f"((c)[2]), "+f"((c)[3])      \
                 : "r"((a)[0]), "r"((a)[1]), "r"((a)[2]), "r"((a)[3]),          \
                   "r"(b0), "r"(b1))

// ===========================================================================
// W -> bf16 hi/lo transposed: g_bh[n][k] = hi(W[k][n]), g_bl = residual
// ===========================================================================
__global__ void k_wconv(const float* __restrict__ W,
                        __nv_bfloat16* __restrict__ bh,
                        __nv_bfloat16* __restrict__ bl) {
    int i = blockIdx.x * 256 + threadIdx.x;   // 65536 threads
    int k = i >> 8;
    int n = i & 255;
    float w = __ldg(W + i);
    __nv_bfloat16 h = __float2bfloat16_rn(w);
    __nv_bfloat16 l = __float2bfloat16_rn(w - __bfloat162float(h));
    bh[n * 256 + k] = h;
    bl[n * 256 + k] = l;
}

// ===========================================================================
// bf16 split-GEMM via mma.sync: xw[M,256] = A[M,256] @ W[256,256]
// CTA 128x128, BK=32, 8 warps of 64x32. SMEM stride 40 bf16 (conflict-free).
// ===========================================================================
#define ASTR 40

__global__ __launch_bounds__(256, 2) void k_gemm_mma(const float* __restrict__ A,
                                                     const __nv_bfloat16* __restrict__ Bh,
                                                     const __nv_bfloat16* __restrict__ Bl,
                                                     float* __restrict__ Cmat, int M) {
    __shared__ __nv_bfloat16 Ahs[128 * ASTR];
    __shared__ __nv_bfloat16 Als[128 * ASTR];
    __shared__ __nv_bfloat16 Bhs[128 * ASTR];
    __shared__ __nv_bfloat16 Bls[128 * ASTR];

    const int tid = threadIdx.x;
    const int wid = tid >> 5;
    const int lane = tid & 31;
    const int g = lane >> 2;
    const int t = lane & 3;
    const int bm = blockIdx.y * 128;
    const int bn = blockIdx.x * 128;
    const int warp_m = (wid >> 2) * 64;
    const int warp_n = (wid & 3) * 32;

    float acc[4][4][4];
#pragma unroll
    for (int i = 0; i < 4; i++)
#pragma unroll
        for (int j = 0; j < 4; j++)
#pragma unroll
            for (int q = 0; q < 4; q++) acc[i][j][q] = 0.f;

    const int sm = tid >> 1;            // staging row (0..127)
    const int skg = (tid & 1) * 16;     // staging k offset (0 or 16)
    const float* ap_base = A + (size_t)min(bm + sm, M - 1) * C + skg;
    const __nv_bfloat16* bhp = Bh + (size_t)(bn + sm) * 256 + skg;
    const __nv_bfloat16* blp = Bl + (size_t)(bn + sm) * 256 + skg;

    for (int kc = 0; kc < 8; kc++) {
        const int k0 = kc * 32;

        // ---- stage A (fp32 -> bf16 hi/lo): 16 k-values per thread ----
#pragma unroll
        for (int q = 0; q < 4; q++) {
            float4 v = __ldg((const float4*)(ap_base + k0) + q);
            __nv_bfloat16 hx = __float2bfloat16_rn(v.x);
            __nv_bfloat16 hy = __float2bfloat16_rn(v.y);
            __nv_bfloat16 hz = __float2bfloat16_rn(v.z);
            __nv_bfloat16 hw = __float2bfloat16_rn(v.w);
            __nv_bfloat16 lx = __float2bfloat16_rn(v.x - __bfloat162float(hx));
            __nv_bfloat16 ly = __float2bfloat16_rn(v.y - __bfloat162float(hy));
            __nv_bfloat16 lz = __float2bfloat16_rn(v.z - __bfloat162float(hz));
            __nv_bfloat16 lw = __float2bfloat16_rn(v.w - __bfloat162float(hw));
            int eo = sm * ASTR + skg + q * 4;
            *(uint2*)&Ahs[eo] = make_uint2(pk(hx, hy), pk(hz, hw));
            *(uint2*)&Als[eo] = make_uint2(pk(lx, ly), pk(lz, lw));
        }
        // ---- stage B (bf16 copy): 16 k-values per thread = 2 x uint4 ----
        {
            int eo = sm * ASTR + skg;
            *(uint4*)&Bhs[eo]     = *(const uint4*)(bhp + k0);
            *(uint4*)&Bhs[eo + 8] = *(const uint4*)(bhp + k0 + 8);
            *(uint4*)&Bls[eo]     = *(const uint4*)(blp + k0);
            *(uint4*)&Bls[eo + 8] = *(const uint4*)(blp + k0 + 8);
        }
        __syncthreads();

#pragma unroll
        for (int ks = 0; ks < 2; ks++) {
            const int koff = ks * 16;
            uint32_t ah[4][4], al[4][4];
#pragma unroll
            for (int i = 0; i < 4; i++) {
                int r0 = (warp_m + i * 16 + g) * ASTR + koff + 2 * t;
                ah[i][0] = *(const uint32_t*)&Ahs[r0];
                ah[i][1] = *(const uint32_t*)&Ahs[r0 + 8 * ASTR];
                ah[i][2] = *(const uint32_t*)&Ahs[r0 + 8];
                ah[i][3] = *(const uint32_t*)&Ahs[r0 + 8 * ASTR + 8];
                al[i][0] = *(const uint32_t*)&Als[r0];
                al[i][1] = *(const uint32_t*)&Als[r0 + 8 * ASTR];
                al[i][2] = *(const uint32_t*)&Als[r0 + 8];
                al[i][3] = *(const uint32_t*)&Als[r0 + 8 * ASTR + 8];
            }
#pragma unroll
            for (int j = 0; j < 4; j++) {
                int rb = (warp_n + j * 8 + g) * ASTR + koff + 2 * t;
                uint32_t bh0 = *(const uint32_t*)&Bhs[rb];
                uint32_t bh1 = *(const uint32_t*)&Bhs[rb + 8];
                uint32_t bl0 = *(const uint32_t*)&Bls[rb];
                uint32_t bl1 = *(const uint32_t*)&Bls[rb + 8];
#pragma unroll
                for (int i = 0; i < 4; i++) {
                    MMA_BF16(acc[i][j], ah[i], bh0, bh1);
                    MMA_BF16(acc[i][j], ah[i], bl0, bl1);
                    MMA_BF16(acc[i][j], al[i], bh0, bh1);
                }
            }
        }
        __syncthreads();
    }

    // ---- epilogue ----
#pragma unroll
    for (int i = 0; i < 4; i++) {
        int r0 = bm + warp_m + i * 16 + g;
        int r1 = r0 + 8;
#pragma unroll
        for (int j = 0; j < 4; j++) {
            int cc = bn + warp_n + j * 8 + 2 * t;
            if (r0 < M)
                *(float2*)(Cmat + (size_t)r0 * C + cc) =
                    make_float2(acc[i][j][0], acc[i][j][1]);
            if (r1 < M)
                *(float2*)(Cmat + (size_t)r1 * C + cc) =
                    make_float2(acc[i][j][2], acc[i][j][3]);
        }
    }
}

// ===========================================================================
// CSR build: histogram, inv-sqrt-degree, multi-block scan, bucket
// ===========================================================================
__global__ void k_zero(int* cnt, int* cursor, int n) {
    int i = blockIdx.x * blockDim.x + threadIdx.x;
    if (i < n) { cnt[i] = 0; cursor[i] = 0; }
}

__global__ void k_hist(const int* __restrict__ col, int* cnt, int E) {
    int i = blockIdx.x * blockDim.x + threadIdx.x;
    if (i < E) atomicAdd(&cnt[col[i]], 1);
}

__global__ void k_inv(const int* __restrict__ cnt, float* __restrict__ inv, int n) {
    int i = blockIdx.x * blockDim.x + threadIdx.x;
    if (i < n) inv[i] = rsqrtf((float)cnt[i] + 1.0f);   // +1 self loop
}

__global__ __launch_bounds__(1024) void k_scan1(const int* __restrict__ cnt,
                                                int* __restrict__ start,
                                                int* __restrict__ bsum, int n) {
    __shared__ int sh[1024];
    int tx = threadIdx.x;
    int i = blockIdx.x * 1024 + tx;
    int v = (i < n) ? cnt[i] : 0;
    sh[tx] = v;
    __syncthreads();
    for (int off = 1; off < 1024; off <<= 1) {
        int tv = (tx >= off) ? sh[tx - off] : 0;
        __syncthreads();
        sh[tx] += tv;
        __syncthreads();
    }
    if (i < n) start[i] = sh[tx] - v;                  // exclusive
    if (tx == 1023) bsum[blockIdx.x] = sh[1023];
}

__global__ __launch_bounds__(128) void k_scan2(int* bsum, int nb) {
    __shared__ int sh[128];
    int tx = threadIdx.x;
    int v = (tx < nb) ? bsum[tx] : 0;
    sh[tx] = v;
    __syncthreads();
    for (int off = 1; off < 128; off <<= 1) {
        int tv = (tx >= off) ? sh[tx - off] : 0;
        __syncthreads();
        sh[tx] += tv;
        __syncthreads();
    }
    if (tx < nb) bsum[tx] = sh[tx] - v;                // exclusive
}

__global__ void k_scan3(const int* __restrict__ bsum, int* __restrict__ start,
                        int n, int E) {
    int i = blockIdx.x * blockDim.x + threadIdx.x;
    if (i < n) start[i] += bsum[i >> 10];
    if (i == 0) start[n] = E;
}

__global__ void k_bucket(const int* __restrict__ row, const int* __restrict__ col,
                         const int* __restrict__ start, int* cursor,
                         int* __restrict__ ebuf, int E) {
    int i = blockIdx.x * blockDim.x + threadIdx.x;
    if (i < E) {
        int c = col[i];
        int p = atomicAdd(&cursor[c], 1);
        ebuf[start[c] + p] = row[i];
    }
}

// ===========================================================================
// Fused aggregation + LayerNorm + ReLU (one warp per node)
// ===========================================================================
__global__ __launch_bounds__(256) void k_agg_ln(const float* __restrict__ xw,
                                                const int* __restrict__ ebuf,
                                                const int* __restrict__ start,
                                                const float* __restrict__ inv,
                                                const float* __restrict__ bias,
                                                const float* __restrict__ gamma,
                                                const float* __restrict__ beta,
                                                float* __restrict__ out) {
    int w = (blockIdx.x * blockDim.x + threadIdx.x) >> 5;
    int lane = threadIdx.x & 31;
    if (w >= N_NODES) return;

    const float invn = __ldg(inv + w);

    const float4* self = (const float4*)(xw + (size_t)w * C);
    float4 a0 = __ldg(self + lane);
    float4 a1 = __ldg(self + lane + 32);
    float4 b0 = ((const float4*)bias)[lane];
    float4 b1 = ((const float4*)bias)[lane + 32];
    float sn = invn * invn;
    a0.x = fmaf(a0.x, sn, b0.x); a0.y = fmaf(a0.y, sn, b0.y);
    a0.z = fmaf(a0.z, sn, b0.z); a0.w = fmaf(a0.w, sn, b0.w);
    a1.x = fmaf(a1.x, sn, b1.x); a1.y = fmaf(a1.y, sn, b1.y);
    a1.z = fmaf(a1.z, sn, b1.z); a1.w = fmaf(a1.w, sn, b1.w);

    const int s = __ldg(start + w);
    const int e = __ldg(start + w + 1);

    for (int base = s; base < e; base += 32) {
        int rem = e - base;
        int r = 0; float nv = 0.f;
        if (lane < rem) {
            r = __ldg(ebuf + base + lane);
            nv = __ldg(inv + r) * invn;
        }
        int cnt = min(rem, 32);
#pragma unroll 2
        for (int j = 0; j < cnt; j++) {
            int rj = __shfl_sync(0xFFFFFFFFu, r, j);
            float nj = __shfl_sync(0xFFFFFFFFu, nv, j);
            const float4* src = (const float4*)(xw + (size_t)rj * C);
            float4 f0 = __ldg(src + lane);
            float4 f1 = __ldg(src + lane + 32);
            a0.x = fmaf(f0.x, nj, a0.x); a0.y = fmaf(f0.y, nj, a0.y);
            a0.z = fmaf(f0.z, nj, a0.z); a0.w = fmaf(f0.w, nj, a0.w);
            a1.x = fmaf(f1.x, nj, a1.x); a1.y = fmaf(f1.y, nj, a1.y);
            a1.z = fmaf(f1.z, nj, a1.z); a1.w = fmaf(f1.w, nj, a1.w);
        }
    }

    float su = a0.x + a0.y + a0.z + a0.w + a1.x + a1.y + a1.z + a1.w;
#pragma unroll
    for (int o = 16; o > 0; o >>= 1) su += __shfl_xor_sync(0xFFFFFFFFu, su, o);
    float mu = su * (1.0f / 256.0f);

    float d, ss = 0.f;
    d = a0.x - mu; ss += d * d;
    d = a0.y - mu; ss += d * d;
    d = a0.z - mu; ss += d * d;
    d = a0.w - mu; ss += d * d;
    d = a1.x - mu; ss += d * d;
    d = a1.y - mu; ss += d * d;
    d = a1.z - mu; ss += d * d;
    d = a1.w - mu; ss += d * d;
#pragma unroll
    for (int o = 16; o > 0; o >>= 1) ss += __shfl_xor_sync(0xFFFFFFFFu, ss, o);
    float rstd = rsqrtf(ss * (1.0f / 256.0f) + EPS);

    float4 g0 = ((const float4*)gamma)[lane];
    float4 g1 = ((const float4*)gamma)[lane + 32];
    float4 e0 = ((const float4*)beta)[lane];
    float4 e1 = ((const float4*)beta)[lane + 32];

    float4 o0, o1;
    o0.x = fmaxf(0.f, (a0.x - mu) * rstd * g0.x + e0.x);
    o0.y = fmaxf(0.f, (a0.y - mu) * rstd * g0.y + e0.y);
    o0.z = fmaxf(0.f, (a0.z - mu) * rstd * g0.z + e0.z);
    o0.w = fmaxf(0.f, (a0.w - mu) * rstd * g0.w + e0.w);
    o1.x = fmaxf(0.f, (a1.x - mu) * rstd * g1.x + e1.x);
    o1.y = fmaxf(0.f, (a1.y - mu) * rstd * g1.y + e1.y);
    o1.z = fmaxf(0.f, (a1.z - mu) * rstd * g1.z + e1.z);
    o1.w = fmaxf(0.f, (a1.w - mu) * rstd * g1.w + e1.w);

    float4* po = (float4*)(out + (size_t)w * C);
    po[lane] = o0;
    po[lane + 32] = o1;
}

// ===========================================================================
// Launch
// ===========================================================================
static void run_layer(const float* xin, const float* W, const float* bias,
                      float* xw, __nv_bfloat16* bh, __nv_bfloat16* bl,
                      const int* ebuf, const int* start,
                      const float* inv, const float* gamma, const float* beta,
                      float* zout) {
    k_wconv<<<C * C / 256, 256>>>(W, bh, bl);
    dim3 grid(2, cdiv(N_NODES, 128));
    k_gemm_mma<<<grid, 256>>>(xin, bh, bl, xw, N_NODES);
    k_agg_ln<<<cdiv(N_NODES * 32, 256), 256>>>(xw, ebuf, start, inv, bias,
                                               gamma, beta, zout);
}

extern "C" void kernel_launch(void* const* d_in, const int* in_sizes, int n_in,
                              void* d_out, int out_size) {
    const float* x     = (const float*)d_in[0];
    const int*   edges = (const int*)d_in[1];
    const float* W1    = (const float*)d_in[2];
    const float* b1    = (const float*)d_in[3];
    const float* W2    = (const float*)d_in[4];
    const float* b2    = (const float*)d_in[5];
    const float* gamma = (const float*)d_in[6];
    const float* beta  = (const float*)d_in[7];
    const int E = in_sizes[1] / 2;
    const int* row = edges;
    const int* col = edges + E;

    float *xw, *inv;
    int *cnt, *cursor, *start, *ebuf, *bsum;
    __nv_bfloat16 *bh, *bl;
    cudaGetSymbolAddress((void**)&xw,     g_xw);
    cudaGetSymbolAddress((void**)&inv,    g_inv);
    cudaGetSymbolAddress((void**)&cnt,    g_cnt);
    cudaGetSymbolAddress((void**)&cursor, g_cursor);
    cudaGetSymbolAddress((void**)&start,  g_start);
    cudaGetSymbolAddress((void**)&ebuf,   g_ebuf);
    cudaGetSymbolAddress((void**)&bsum,   g_bsum);
    cudaGetSymbolAddress((void**)&bh,     g_bh);
    cudaGetSymbolAddress((void**)&bl,     g_bl);

    float* z1 = (float*)d_out;
    float* z2 = (float*)d_out + (size_t)N_NODES * C;

    // CSR build
    k_zero<<<cdiv(N_NODES, 256), 256>>>(cnt, cursor, N_NODES);
    k_hist<<<cdiv(E, 256), 256>>>(col, cnt, E);
    k_inv<<<cdiv(N_NODES, 256), 256>>>(cnt, inv, N_NODES);
    int nb = cdiv(N_NODES, 1024);
    k_scan1<<<nb, 1024>>>(cnt, start, bsum, N_NODES);
    k_scan2<<<1, 128>>>(bsum, nb);
    k_scan3<<<cdiv(N_NODES, 256), 256>>>(bsum, start, N_NODES, E);
    k_bucket<<<cdiv(E, 256), 256>>>(row, col, start, cursor, ebuf, E);

    run_layer(x,  W1, b1, xw, bh, bl, ebuf, start, inv, gamma, beta, z1);
    run_layer(z1, W2, b2, xw, bh, bl, ebuf, start, inv, gamma, beta, z2);
}

// round 6
// speedup vs baseline: 3.0663x; 1.2271x over previous
#include <cuda_runtime.h>
#include <cuda_bf16.h>
#include <cuda_fp16.h>
#include <cstdint>

#define N_NODES 100000
#define C 256
#define EPS 1e-5f
#define E_MAX 1700000

// Scratch (device globals — no runtime allocation allowed)
__device__ __half g_xwh[(size_t)N_NODES * C];   // xw in fp16 (gather-compressed)
__device__ float g_inv[N_NODES];
__device__ int   g_cnt[N_NODES];
__device__ int   g_cursor[N_NODES];
__device__ int   g_start[N_NODES + 1];
__device__ int   g_ebuf[E_MAX];
__device__ int   g_bsum[128];
__device__ __nv_bfloat16 g_bh[C * C];   // W^T hi, [n][k]
__device__ __nv_bfloat16 g_bl[C * C];   // W^T lo, [n][k]

static inline int cdiv(int a, int b) { return (a + b - 1) / b; }

__device__ __forceinline__ uint32_t pk(__nv_bfloat16 a, __nv_bfloat16 b) {
    __nv_bfloat162 t(a, b);
    return *(uint32_t*)&t;
}

#define MMA_BF16(c, a, b0, b1)                                                  \
    asm volatile("mma.sync.aligned.m16n8k16.row.col.f32.bf16.bf16.f32 "        \
                 "{%0,%1,%2,%3},{%4,%5,%6,%7},{%8,%9},{%0,%1,%2,%3};"          \
                 : "+f"((c)[0]), "+f"((c)[1]), "+f"((c)[2]), "+f"((c)[3])      \
                 : "r"((a)[0]), "r"((a)[1]), "r"((a)[2]), "r"((a)[3]),          \
                   "r"(b0), "r"(b1))

#define LDSM_X4(r0, r1, r2, r3, addr)                                           \
    asm volatile("ldmatrix.sync.aligned.m8n8.x4.shared.b16 {%0,%1,%2,%3}, [%4];" \
                 : "=r"(r0), "=r"(r1), "=r"(r2), "=r"(r3) : "r"(addr))

// ===========================================================================
// W -> bf16 hi/lo transposed: g_bh[n][k] = hi(W[k][n]), g_bl = residual
// ===========================================================================
__global__ void k_wconv(const float* __restrict__ W,
                        __nv_bfloat16* __restrict__ bh,
                        __nv_bfloat16* __restrict__ bl) {
    int i = blockIdx.x * 256 + threadIdx.x;   // 65536 threads
    int k = i >> 8;
    int n = i & 255;
    float w = __ldg(W + i);
    __nv_bfloat16 h = __float2bfloat16_rn(w);
    __nv_bfloat16 l = __float2bfloat16_rn(w - __bfloat162float(h));
    bh[n * 256 + k] = h;
    bl[n * 256 + k] = l;
}

// ===========================================================================
// bf16 split-GEMM via mma.sync + ldmatrix: xwh[M,256] = half(A[M,256] @ W)
// CTA 128x128, BK=32, 8 warps of 64x32. SMEM stride 40 bf16 (conflict-free).
// ===========================================================================
#define ASTR 40

__global__ __launch_bounds__(256, 2) void k_gemm_mma(const float* __restrict__ A,
                                                     const __nv_bfloat16* __restrict__ Bh,
                                                     const __nv_bfloat16* __restrict__ Bl,
                                                     __half* __restrict__ Cmat, int M) {
    __shared__ __nv_bfloat16 Ahs[128 * ASTR];
    __shared__ __nv_bfloat16 Als[128 * ASTR];
    __shared__ __nv_bfloat16 Bhs[128 * ASTR];
    __shared__ __nv_bfloat16 Bls[128 * ASTR];

    const int tid = threadIdx.x;
    const int wid = tid >> 5;
    const int lane = tid & 31;
    const int g = lane >> 2;
    const int t = lane & 3;
    const int bm = blockIdx.y * 128;
    const int bn = blockIdx.x * 128;
    const int warp_m = (wid >> 2) * 64;
    const int warp_n = (wid & 3) * 32;

    const uint32_t ahs_b = (uint32_t)__cvta_generic_to_shared(Ahs);
    const uint32_t als_b = (uint32_t)__cvta_generic_to_shared(Als);
    const uint32_t bhs_b = (uint32_t)__cvta_generic_to_shared(Bhs);
    const uint32_t bls_b = (uint32_t)__cvta_generic_to_shared(Bls);

    // ldmatrix lane-address components
    const int a_r = lane & 15;                 // row within 16
    const int a_kh = (lane >> 4) << 3;         // k half (0 or 8)
    const int b_rn = (lane & 7) + ((lane >> 4) << 3);  // n row within 16
    const int b_kh = ((lane >> 3) & 1) << 3;   // k half (0 or 8)

    float acc[4][4][4];
#pragma unroll
    for (int i = 0; i < 4; i++)
#pragma unroll
        for (int j = 0; j < 4; j++)
#pragma unroll
            for (int q = 0; q < 4; q++) acc[i][j][q] = 0.f;

    const int sm = tid >> 1;            // staging row (0..127)
    const int skg = (tid & 1) * 16;     // staging k offset (0 or 16)
    const float* ap_base = A + (size_t)min(bm + sm, M - 1) * C + skg;
    const __nv_bfloat16* bhp = Bh + (size_t)(bn + sm) * 256 + skg;
    const __nv_bfloat16* blp = Bl + (size_t)(bn + sm) * 256 + skg;

    for (int kc = 0; kc < 8; kc++) {
        const int k0 = kc * 32;

        // ---- stage A (fp32 -> bf16 hi/lo): 16 k-values per thread ----
#pragma unroll
        for (int q = 0; q < 4; q++) {
            float4 v = __ldg((const float4*)(ap_base + k0) + q);
            __nv_bfloat16 hx = __float2bfloat16_rn(v.x);
            __nv_bfloat16 hy = __float2bfloat16_rn(v.y);
            __nv_bfloat16 hz = __float2bfloat16_rn(v.z);
            __nv_bfloat16 hw = __float2bfloat16_rn(v.w);
            __nv_bfloat16 lx = __float2bfloat16_rn(v.x - __bfloat162float(hx));
            __nv_bfloat16 ly = __float2bfloat16_rn(v.y - __bfloat162float(hy));
            __nv_bfloat16 lz = __float2bfloat16_rn(v.z - __bfloat162float(hz));
            __nv_bfloat16 lw = __float2bfloat16_rn(v.w - __bfloat162float(hw));
            int eo = sm * ASTR + skg + q * 4;
            *(uint2*)&Ahs[eo] = make_uint2(pk(hx, hy), pk(hz, hw));
            *(uint2*)&Als[eo] = make_uint2(pk(lx, ly), pk(lz, lw));
        }
        // ---- stage B (bf16 copy): 16 k-values per thread = 2 x uint4 ----
        {
            int eo = sm * ASTR + skg;
            *(uint4*)&Bhs[eo]     = *(const uint4*)(bhp + k0);
            *(uint4*)&Bhs[eo + 8] = *(const uint4*)(bhp + k0 + 8);
            *(uint4*)&Bls[eo]     = *(const uint4*)(blp + k0);
            *(uint4*)&Bls[eo + 8] = *(const uint4*)(blp + k0 + 8);
        }
        __syncthreads();

#pragma unroll
        for (int ks = 0; ks < 2; ks++) {
            const int koff = ks * 16;

            // A fragments via ldmatrix.x4 (hi & lo)
            uint32_t ah[4][4], al[4][4];
            const uint32_t a_off =
                (uint32_t)(((warp_m + a_r) * ASTR + koff + a_kh) * 2);
#pragma unroll
            for (int i = 0; i < 4; i++) {
                uint32_t ao = a_off + (uint32_t)(i * 16 * ASTR * 2);
                LDSM_X4(ah[i][0], ah[i][1], ah[i][2], ah[i][3], ahs_b + ao);
                LDSM_X4(al[i][0], al[i][1], al[i][2], al[i][3], als_b + ao);
            }
            // B fragments via ldmatrix.x4 (two j-tiles per load)
            uint32_t bhf[2][4], blf[2][4];
            const uint32_t b_off =
                (uint32_t)(((warp_n + b_rn) * ASTR + koff + b_kh) * 2);
#pragma unroll
            for (int j2 = 0; j2 < 2; j2++) {
                uint32_t bo = b_off + (uint32_t)(j2 * 16 * ASTR * 2);
                LDSM_X4(bhf[j2][0], bhf[j2][1], bhf[j2][2], bhf[j2][3], bhs_b + bo);
                LDSM_X4(blf[j2][0], blf[j2][1], blf[j2][2], blf[j2][3], bls_b + bo);
            }

#pragma unroll
            for (int j = 0; j < 4; j++) {
                uint32_t bh0 = bhf[j >> 1][(j & 1) * 2];
                uint32_t bh1 = bhf[j >> 1][(j & 1) * 2 + 1];
                uint32_t bl0 = blf[j >> 1][(j & 1) * 2];
                uint32_t bl1 = blf[j >> 1][(j & 1) * 2 + 1];
#pragma unroll
                for (int i = 0; i < 4; i++) {
                    MMA_BF16(acc[i][j], ah[i], bh0, bh1);
                    MMA_BF16(acc[i][j], ah[i], bl0, bl1);
                    MMA_BF16(acc[i][j], al[i], bh0, bh1);
                }
            }
        }
        __syncthreads();
    }

    // ---- epilogue: fp32 acc -> fp16 store ----
#pragma unroll
    for (int i = 0; i < 4; i++) {
        int r0 = bm + warp_m + i * 16 + g;
        int r1 = r0 + 8;
#pragma unroll
        for (int j = 0; j < 4; j++) {
            int cc = bn + warp_n + j * 8 + 2 * t;
            if (r0 < M)
                *(__half2*)(Cmat + (size_t)r0 * C + cc) =
                    __floats2half2_rn(acc[i][j][0], acc[i][j][1]);
            if (r1 < M)
                *(__half2*)(Cmat + (size_t)r1 * C + cc) =
                    __floats2half2_rn(acc[i][j][2], acc[i][j][3]);
        }
    }
}

// ===========================================================================
// CSR build: histogram, inv-sqrt-degree, multi-block scan, bucket
// ===========================================================================
__global__ void k_zero(int* cnt, int* cursor, int n) {
    int i = blockIdx.x * blockDim.x + threadIdx.x;
    if (i < n) { cnt[i] = 0; cursor[i] = 0; }
}

__global__ void k_hist(const int* __restrict__ col, int* cnt, int E) {
    int i = blockIdx.x * blockDim.x + threadIdx.x;
    if (i < E) atomicAdd(&cnt[col[i]], 1);
}

__global__ void k_inv(const int* __restrict__ cnt, float* __restrict__ inv, int n) {
    int i = blockIdx.x * blockDim.x + threadIdx.x;
    if (i < n) inv[i] = rsqrtf((float)cnt[i] + 1.0f);   // +1 self loop
}

__global__ __launch_bounds__(1024) void k_scan1(const int* __restrict__ cnt,
                                                int* __restrict__ start,
                                                int* __restrict__ bsum, int n) {
    __shared__ int sh[1024];
    int tx = threadIdx.x;
    int i = blockIdx.x * 1024 + tx;
    int v = (i < n) ? cnt[i] : 0;
    sh[tx] = v;
    __syncthreads();
    for (int off = 1; off < 1024; off <<= 1) {
        int tv = (tx >= off) ? sh[tx - off] : 0;
        __syncthreads();
        sh[tx] += tv;
        __syncthreads();
    }
    if (i < n) start[i] = sh[tx] - v;                  // exclusive
    if (tx == 1023) bsum[blockIdx.x] = sh[1023];
}

__global__ __launch_bounds__(128) void k_scan2(int* bsum, int nb) {
    __shared__ int sh[128];
    int tx = threadIdx.x;
    int v = (tx < nb) ? bsum[tx] : 0;
    sh[tx] = v;
    __syncthreads();
    for (int off = 1; off < 128; off <<= 1) {
        int tv = (tx >= off) ? sh[tx - off] : 0;
        __syncthreads();
        sh[tx] += tv;
        __syncthreads();
    }
    if (tx < nb) bsum[tx] = sh[tx] - v;                // exclusive
}

__global__ void k_scan3(const int* __restrict__ bsum, int* __restrict__ start,
                        int n, int E) {
    int i = blockIdx.x * blockDim.x + threadIdx.x;
    if (i < n) start[i] += bsum[i >> 10];
    if (i == 0) start[n] = E;
}

__global__ void k_bucket(const int* __restrict__ row, const int* __restrict__ col,
                         const int* __restrict__ start, int* cursor,
                         int* __restrict__ ebuf, int E) {
    int i = blockIdx.x * blockDim.x + threadIdx.x;
    if (i < E) {
        int c = col[i];
        int p = atomicAdd(&cursor[c], 1);
        ebuf[start[c] + p] = row[i];
    }
}

// ===========================================================================
// Fused aggregation (fp16 gather) + LayerNorm + ReLU (one warp per node)
// Each lane owns 8 contiguous channels [8*lane, 8*lane+8).
// ===========================================================================
__global__ __launch_bounds__(256) void k_agg_ln(const __half* __restrict__ xwh,
                                                const int* __restrict__ ebuf,
                                                const int* __restrict__ start,
                                                const float* __restrict__ inv,
                                                const float* __restrict__ bias,
                                                const float* __restrict__ gamma,
                                                const float* __restrict__ beta,
                                                float* __restrict__ out) {
    int w = (blockIdx.x * blockDim.x + threadIdx.x) >> 5;
    int lane = threadIdx.x & 31;
    if (w >= N_NODES) return;

    const float invn = __ldg(inv + w);
    const float sn = invn * invn;

    float a[8];
    {
        uint4 raw = __ldg((const uint4*)(xwh + (size_t)w * C) + lane);
        float4 b0 = ((const float4*)bias)[2 * lane];
        float4 b1 = ((const float4*)bias)[2 * lane + 1];
        float2 f0 = __half22float2(*(__half2*)&raw.x);
        float2 f1 = __half22float2(*(__half2*)&raw.y);
        float2 f2 = __half22float2(*(__half2*)&raw.z);
        float2 f3 = __half22float2(*(__half2*)&raw.w);
        a[0] = fmaf(f0.x, sn, b0.x); a[1] = fmaf(f0.y, sn, b0.y);
        a[2] = fmaf(f1.x, sn, b0.z); a[3] = fmaf(f1.y, sn, b0.w);
        a[4] = fmaf(f2.x, sn, b1.x); a[5] = fmaf(f2.y, sn, b1.y);
        a[6] = fmaf(f3.x, sn, b1.z); a[7] = fmaf(f3.y, sn, b1.w);
    }

    const int s = __ldg(start + w);
    const int e = __ldg(start + w + 1);

    for (int base = s; base < e; base += 32) {
        int rem = e - base;
        int r = 0; float nv = 0.f;
        if (lane < rem) {
            r = __ldg(ebuf + base + lane);
            nv = __ldg(inv + r) * invn;
        }
        int cnt = min(rem, 32);
#pragma unroll 2
        for (int j = 0; j < cnt; j++) {
            int rj = __shfl_sync(0xFFFFFFFFu, r, j);
            float nj = __shfl_sync(0xFFFFFFFFu, nv, j);
            uint4 raw = __ldg((const uint4*)(xwh + (size_t)rj * C) + lane);
            float2 f0 = __half22float2(*(__half2*)&raw.x);
            float2 f1 = __half22float2(*(__half2*)&raw.y);
            float2 f2 = __half22float2(*(__half2*)&raw.z);
            float2 f3 = __half22float2(*(__half2*)&raw.w);
            a[0] = fmaf(f0.x, nj, a[0]); a[1] = fmaf(f0.y, nj, a[1]);
            a[2] = fmaf(f1.x, nj, a[2]); a[3] = fmaf(f1.y, nj, a[3]);
            a[4] = fmaf(f2.x, nj, a[4]); a[5] = fmaf(f2.y, nj, a[5]);
            a[6] = fmaf(f3.x, nj, a[6]); a[7] = fmaf(f3.y, nj, a[7]);
        }
    }

    // LayerNorm + ReLU
    float su = a[0] + a[1] + a[2] + a[3] + a[4] + a[5] + a[6] + a[7];
#pragma unroll
    for (int o = 16; o > 0; o >>= 1) su += __shfl_xor_sync(0xFFFFFFFFu, su, o);
    float mu = su * (1.0f / 256.0f);

    float ss = 0.f;
#pragma unroll
    for (int q = 0; q < 8; q++) { float d = a[q] - mu; ss += d * d; }
#pragma unroll
    for (int o = 16; o > 0; o >>= 1) ss += __shfl_xor_sync(0xFFFFFFFFu, ss, o);
    float rstd = rsqrtf(ss * (1.0f / 256.0f) + EPS);

    float4 g0 = ((const float4*)gamma)[2 * lane];
    float4 g1 = ((const float4*)gamma)[2 * lane + 1];
    float4 e0 = ((const float4*)beta)[2 * lane];
    float4 e1 = ((const float4*)beta)[2 * lane + 1];

    float4 o0, o1;
    o0.x = fmaxf(0.f, (a[0] - mu) * rstd * g0.x + e0.x);
    o0.y = fmaxf(0.f, (a[1] - mu) * rstd * g0.y + e0.y);
    o0.z = fmaxf(0.f, (a[2] - mu) * rstd * g0.z + e0.z);
    o0.w = fmaxf(0.f, (a[3] - mu) * rstd * g0.w + e0.w);
    o1.x = fmaxf(0.f, (a[4] - mu) * rstd * g1.x + e1.x);
    o1.y = fmaxf(0.f, (a[5] - mu) * rstd * g1.y + e1.y);
    o1.z = fmaxf(0.f, (a[6] - mu) * rstd * g1.z + e1.z);
    o1.w = fmaxf(0.f, (a[7] - mu) * rstd * g1.w + e1.w);

    float4* po = (float4*)(out + (size_t)w * C);
    po[2 * lane] = o0;
    po[2 * lane + 1] = o1;
}

// ===========================================================================
// Launch
// ===========================================================================
static void run_layer(const float* xin, const float* W, const float* bias,
                      __half* xwh, __nv_bfloat16* bh, __nv_bfloat16* bl,
                      const int* ebuf, const int* start,
                      const float* inv, const float* gamma, const float* beta,
                      float* zout) {
    k_wconv<<<C * C / 256, 256>>>(W, bh, bl);
    dim3 grid(2, cdiv(N_NODES, 128));
    k_gemm_mma<<<grid, 256>>>(xin, bh, bl, xwh, N_NODES);
    k_agg_ln<<<cdiv(N_NODES * 32, 256), 256>>>(xwh, ebuf, start, inv, bias,
                                               gamma, beta, zout);
}

extern "C" void kernel_launch(void* const* d_in, const int* in_sizes, int n_in,
                              void* d_out, int out_size) {
    const float* x     = (const float*)d_in[0];
    const int*   edges = (const int*)d_in[1];
    const float* W1    = (const float*)d_in[2];
    const float* b1    = (const float*)d_in[3];
    const float* W2    = (const float*)d_in[4];
    const float* b2    = (const float*)d_in[5];
    const float* gamma = (const float*)d_in[6];
    const float* beta  = (const float*)d_in[7];
    const int E = in_sizes[1] / 2;
    const int* row = edges;
    const int* col = edges + E;

    float *inv;
    __half *xwh;
    int *cnt, *cursor, *start, *ebuf, *bsum;
    __nv_bfloat16 *bh, *bl;
    cudaGetSymbolAddress((void**)&xwh,    g_xwh);
    cudaGetSymbolAddress((void**)&inv,    g_inv);
    cudaGetSymbolAddress((void**)&cnt,    g_cnt);
    cudaGetSymbolAddress((void**)&cursor, g_cursor);
    cudaGetSymbolAddress((void**)&start,  g_start);
    cudaGetSymbolAddress((void**)&ebuf,   g_ebuf);
    cudaGetSymbolAddress((void**)&bsum,   g_bsum);
    cudaGetSymbolAddress((void**)&bh,     g_bh);
    cudaGetSymbolAddress((void**)&bl,     g_bl);

    float* z1 = (float*)d_out;
    float* z2 = (float*)d_out + (size_t)N_NODES * C;

    // CSR build
    k_zero<<<cdiv(N_NODES, 256), 256>>>(cnt, cursor, N_NODES);
    k_hist<<<cdiv(E, 256), 256>>>(col, cnt, E);
    k_inv<<<cdiv(N_NODES, 256), 256>>>(cnt, inv, N_NODES);
    int nb = cdiv(N_NODES, 1024);
    k_scan1<<<nb, 1024>>>(cnt, start, bsum, N_NODES);
    k_scan2<<<1, 128>>>(bsum, nb);
    k_scan3<<<cdiv(N_NODES, 256), 256>>>(bsum, start, N_NODES, E);
    k_bucket<<<cdiv(E, 256), 256>>>(row, col, start, cursor, ebuf, E);

    run_layer(x,  W1, b1, xwh, bh, bl, ebuf, start, inv, gamma, beta, z1);
    run_layer(z1, W2, b2, xwh, bh, bl, ebuf, start, inv, gamma, beta, z2);
}